// round 14
// baseline (speedup 1.0000x reference)
#include <cuda_runtime.h>
#include <cuda_bf16.h>
#include <cuda_fp16.h>
#include <cstdint>

#define BB 4
#define TSZ 1024
#define DD 512
#define PP 64
#define MM 256

// Scratch (static device memory; no allocation at runtime)
__device__ float g_a1[BB * TSZ * PP];            // x@W1 + b1 + w3e   (t-side)
__device__ float g_a2[BB * TSZ * PP];            // x@W2 + b2         (u-side)
__device__ float g_w3e[BB * PP];                 // ec@W3 + b3
__device__ float g_att[(size_t)BB * TSZ * TSZ];  // raw scores (16 MB)
// fp16 planes (uint4 arrays for 16B alignment)
__device__ uint4 g_attP4[(size_t)BB * TSZ * TSZ / 8];  // probs fp16 (8 MB)
__device__ uint4 g_xT4[(size_t)BB * DD * TSZ / 8];     // x^T  fp16 (4 MB)

// single-MUFU tanh (MUFU.TANH)
__device__ __forceinline__ float fast_tanh(float x) {
    float y;
    asm("tanh.approx.f32 %0, %1;" : "=f"(y) : "f"(x));
    return y;
}

// ---------------------------------------------------------------- K0: w3e
__global__ void k0_w3e(const float* __restrict__ ec,
                       const float* __restrict__ W3,
                       const float* __restrict__ b3) {
    int tid = threadIdx.x;            // 256 threads: (b,p)
    int b = tid >> 6, p = tid & 63;
    float s = b3[p];
    const float* e = ec + b * MM;
#pragma unroll 8
    for (int m = 0; m < MM; m++) s = fmaf(e[m], W3[m * PP + p], s);
    g_w3e[tid] = s;
}

// ------------------------------- KX: transpose x -> fp16 [b][d][t]
__global__ __launch_bounds__(256) void kx_split(const float* __restrict__ x) {
    __shared__ float tile[32][33];
    int b = blockIdx.z;
    int t0 = blockIdx.y * 32, d0 = blockIdx.x * 32;
    int tx = threadIdx.x & 31, ty = threadIdx.x >> 5;  // 32 x 8
    const float* src = x + (size_t)b * TSZ * DD;
#pragma unroll
    for (int i = 0; i < 4; i++)
        tile[ty + 8 * i][tx] = src[(size_t)(t0 + ty + 8 * i) * DD + d0 + tx];
    __syncthreads();
    __half* oh = (__half*)g_xT4 + (size_t)b * DD * TSZ;
#pragma unroll
    for (int i = 0; i < 4; i++) {
        int d = d0 + ty + 8 * i;
        oh[(size_t)d * TSZ + t0 + tx] = __float2half_rn(tile[tx][ty + 8 * i]);
    }
}

// ------------------------------------------------- K1: fused projections
__global__ __launch_bounds__(256) void k1_proj(const float* __restrict__ x,
                                               const float* __restrict__ W1,
                                               const float* __restrict__ b1,
                                               const float* __restrict__ W2,
                                               const float* __restrict__ b2) {
    __shared__ float XsT[32][68];
    __shared__ float W1s[32][64];
    __shared__ float W2s[32][64];
    int tid = threadIdx.x;
    int r0 = blockIdx.x * 64;
    int tx = tid & 15, ty = tid >> 4;
    float acc1[4][4] = {}, acc2[4][4] = {};

    for (int k0 = 0; k0 < DD; k0 += 32) {
        __syncthreads();
#pragma unroll
        for (int s = 0; s < 2; s++) {
            int f = tid + 256 * s;
            int row = f >> 3, q = f & 7;
            float4 v = *(const float4*)(x + (size_t)(r0 + row) * DD + k0 + q * 4);
            XsT[q * 4 + 0][row] = v.x;
            XsT[q * 4 + 1][row] = v.y;
            XsT[q * 4 + 2][row] = v.z;
            XsT[q * 4 + 3][row] = v.w;
        }
#pragma unroll
        for (int s = 0; s < 2; s++) {
            int row = (tid >> 4) + 16 * s;
            int q = tid & 15;
            *(float4*)&W1s[row][q * 4] =
                *(const float4*)(W1 + (size_t)(k0 + row) * PP + q * 4);
            *(float4*)&W2s[row][q * 4] =
                *(const float4*)(W2 + (size_t)(k0 + row) * PP + q * 4);
        }
        __syncthreads();
#pragma unroll
        for (int kk = 0; kk < 32; kk++) {
            float4 a = *(float4*)&XsT[kk][ty * 4];
            float4 u = *(float4*)&W1s[kk][tx * 4];
            float4 w = *(float4*)&W2s[kk][tx * 4];
            float av[4] = {a.x, a.y, a.z, a.w};
            float uv[4] = {u.x, u.y, u.z, u.w};
            float wv[4] = {w.x, w.y, w.z, w.w};
#pragma unroll
            for (int i = 0; i < 4; i++)
#pragma unroll
                for (int j = 0; j < 4; j++) {
                    acc1[i][j] = fmaf(av[i], uv[j], acc1[i][j]);
                    acc2[i][j] = fmaf(av[i], wv[j], acc2[i][j]);
                }
        }
    }
    int b = r0 >> 10;
    float4 vb1 = *(const float4*)(b1 + tx * 4);
    float4 vb2 = *(const float4*)(b2 + tx * 4);
    float4 v3 = *(const float4*)(g_w3e + b * PP + tx * 4);
#pragma unroll
    for (int i = 0; i < 4; i++) {
        int row = r0 + ty * 4 + i;
        float4 o1, o2;
        o1.x = acc1[i][0] + vb1.x + v3.x;
        o1.y = acc1[i][1] + vb1.y + v3.y;
        o1.z = acc1[i][2] + vb1.z + v3.z;
        o1.w = acc1[i][3] + vb1.w + v3.w;
        o2.x = acc2[i][0] + vb2.x;
        o2.y = acc2[i][1] + vb2.y;
        o2.z = acc2[i][2] + vb2.z;
        o2.w = acc2[i][3] + vb2.w;
        *(float4*)(g_a1 + (size_t)row * PP + tx * 4) = o1;
        *(float4*)(g_a2 + (size_t)row * PP + tx * 4) = o2;
    }
}

// ---------------------------------------------- K2: attention scores (MUFU-bound)
__global__ __launch_bounds__(256) void k2_scores(const float* __restrict__ wa) {
    __shared__ float As[32][65];
    __shared__ float Bs[32][65];
    __shared__ float was[64];
    int tid = threadIdx.x;
    int b = blockIdx.z, t0 = blockIdx.y * 32, u0 = blockIdx.x * 32;
    const float* slabA = g_a1 + (size_t)(b * TSZ + t0) * PP;
    const float* slabB = g_a2 + (size_t)(b * TSZ + u0) * PP;
#pragma unroll
    for (int s = 0; s < 8; s++) {
        int f = tid + 256 * s;
        As[f >> 6][f & 63] = slabA[f];
        Bs[f >> 6][f & 63] = slabB[f];
    }
    if (tid < 64) was[tid] = wa[tid];
    __syncthreads();

    int tu = tid & 15, tt = tid >> 4;
    float a00 = 0.f, a01 = 0.f, a10 = 0.f, a11 = 0.f;
#pragma unroll 8
    for (int p = 0; p < 64; p++) {
        float w = was[p];
        float x0 = As[tt][p], x1 = As[tt + 16][p];
        float y0 = Bs[tu][p], y1 = Bs[tu + 16][p];
        a00 = fmaf(w, fast_tanh(x0 + y0), a00);
        a01 = fmaf(w, fast_tanh(x0 + y1), a01);
        a10 = fmaf(w, fast_tanh(x1 + y0), a10);
        a11 = fmaf(w, fast_tanh(x1 + y1), a11);
    }
    float* o0 = g_att + ((size_t)(b * TSZ + t0 + tt)) * TSZ + u0;
    float* o1 = g_att + ((size_t)(b * TSZ + t0 + tt + 16)) * TSZ + u0;
    o0[tu] = a00;
    o0[tu + 16] = a01;
    o1[tu] = a10;
    o1[tu + 16] = a11;
}

// ---------------------- K3: softmax, writes fp16 prob plane
__global__ __launch_bounds__(256) void k3_softmax() {
    int row = blockIdx.x;  // flat (b*T + t)
    const float* p = g_att + (size_t)row * TSZ;
    int tid = threadIdx.x;
    float v0 = p[tid], v1 = p[tid + 256], v2 = p[tid + 512], v3 = p[tid + 768];
    float m = fmaxf(fmaxf(v0, v1), fmaxf(v2, v3));
#pragma unroll
    for (int o = 16; o; o >>= 1) m = fmaxf(m, __shfl_xor_sync(0xffffffffu, m, o));
    __shared__ float red[8];
    __shared__ float bc[2];
    if ((tid & 31) == 0) red[tid >> 5] = m;
    __syncthreads();
    if (tid == 0) {
        float mm = red[0];
#pragma unroll
        for (int i = 1; i < 8; i++) mm = fmaxf(mm, red[i]);
        bc[0] = mm;
    }
    __syncthreads();
    m = bc[0];
    const float L2E = 1.4426950408889634f;
    float e0, e1, e2, e3;
    asm("ex2.approx.f32 %0, %1;" : "=f"(e0) : "f"((v0 - m) * L2E));
    asm("ex2.approx.f32 %0, %1;" : "=f"(e1) : "f"((v1 - m) * L2E));
    asm("ex2.approx.f32 %0, %1;" : "=f"(e2) : "f"((v2 - m) * L2E));
    asm("ex2.approx.f32 %0, %1;" : "=f"(e3) : "f"((v3 - m) * L2E));
    float s = e0 + e1 + e2 + e3;
#pragma unroll
    for (int o = 16; o; o >>= 1) s += __shfl_xor_sync(0xffffffffu, s, o);
    if ((tid & 31) == 0) red[tid >> 5] = s;
    __syncthreads();
    if (tid == 0) {
        float ss = 0.f;
#pragma unroll
        for (int i = 0; i < 8; i++) ss += red[i];
        bc[1] = 1.0f / ss;
    }
    __syncthreads();
    float inv = bc[1];
    __half* oh = (__half*)g_attP4 + (size_t)row * TSZ;
    oh[tid] = __float2half_rn(e0 * inv);
    oh[tid + 256] = __float2half_rn(e1 * inv);
    oh[tid + 512] = __float2half_rn(e2 * inv);
    oh[tid + 768] = __float2half_rn(e3 * inv);
}

// ================ K4: out = probs @ inputs via fp16 mma.sync =================
// Block tile 128x128, BK=32; 8 warps in 2(M)x4(N); warp tile 64x32.
// 4-stage cp.async ring: loads issued 3 chunks ahead; wait_group 2 at chunk
// top -> each load has ~3 mma phases to land (covers DRAM latency).
// SMEM plane: 128 rows x 80B, XOR swizzle bits[4:5] by (row>>3)&3.

__device__ __forceinline__ uint32_t smem_u32(const void* p) {
    uint32_t a;
    asm("{ .reg .u64 t; cvta.to.shared.u64 t, %1; cvt.u32.u64 %0, t; }"
        : "=r"(a) : "l"(p));
    return a;
}
__device__ __forceinline__ uint32_t swz(uint32_t row, uint32_t byteoff) {
    return row * 80u + (byteoff ^ ((row & 24u) << 1));
}
__device__ __forceinline__ void ldsm4(uint32_t r[4], uint32_t addr) {
    asm volatile(
        "ldmatrix.sync.aligned.m8n8.x4.shared.b16 {%0,%1,%2,%3}, [%4];"
        : "=r"(r[0]), "=r"(r[1]), "=r"(r[2]), "=r"(r[3]) : "r"(addr));
}
__device__ __forceinline__ void mma_f16(float c[4], const uint32_t a[4],
                                        uint32_t b0, uint32_t b1) {
    asm volatile(
        "mma.sync.aligned.m16n8k16.row.col.f32.f16.f16.f32 "
        "{%0,%1,%2,%3}, {%4,%5,%6,%7}, {%8,%9}, {%0,%1,%2,%3};"
        : "+f"(c[0]), "+f"(c[1]), "+f"(c[2]), "+f"(c[3])
        : "r"(a[0]), "r"(a[1]), "r"(a[2]), "r"(a[3]), "r"(b0), "r"(b1));
}
__device__ __forceinline__ void cpasync16(uint32_t dst, const void* src) {
    asm volatile("cp.async.cg.shared.global [%0], [%1], 16;"
                 :: "r"(dst), "l"(src) : "memory");
}

#define PLANE 10240u              // 128 * 80
#define BUFSZ (2u * PLANE)        // A, B
#define NSTAGE 4
#define K4_DSMEM (NSTAGE * BUFSZ) // 81920 B

__global__ __launch_bounds__(256) void k4_out_mma(float* __restrict__ out) {
    extern __shared__ uint8_t dsm[];
    uint32_t base0 = smem_u32(dsm);

    int tid = threadIdx.x, wid = tid >> 5, lane = tid & 31;
    int b = blockIdx.z, t0 = blockIdx.y * 128, d0 = blockIdx.x * 128;
    int warp_m = wid >> 2, warp_n = wid & 3;

    // fp16 plane pointers (row pitch = TSZ halves = 2048 B)
    const char* A = (const char*)g_attP4 + ((size_t)(b * TSZ + t0) * TSZ) * 2;
    const char* B = (const char*)g_xT4 + ((size_t)b * DD + d0) * TSZ * 2;

    int row = tid >> 1;                 // 0..127 (A: t-row, B: d-column)
    uint32_t q0 = (tid & 1) * 32;       // byte offset within 64B row seg
    size_t goff = (size_t)row * 2048 + q0;
    uint32_t sw0 = swz(row, q0), sw1 = swz(row, q0 + 16);

    float acc[4][4][4] = {};

    int mi = lane >> 3, r8 = lane & 7;
    uint32_t a_rb = warp_m * 64 + (mi & 1) * 8 + r8;
    uint32_t a_kb0 = (mi >> 1) * 16;
    uint32_t b_rb = warp_n * 32 + ((mi >> 1) & 1) * 8 + r8;
    uint32_t b_kb0 = (mi & 1) * 16;

    // prologue: issue chunks 0..2 into stages 0..2
#pragma unroll
    for (int ch = 0; ch < NSTAGE - 1; ch++) {
        uint32_t bb = base0 + ch * BUFSZ;
        size_t g = goff + (size_t)ch * 64;
        cpasync16(bb + sw0, A + g);
        cpasync16(bb + sw1, A + g + 16);
        cpasync16(bb + PLANE + sw0, B + g);
        cpasync16(bb + PLANE + sw1, B + g + 16);
        asm volatile("cp.async.commit_group;" ::: "memory");
    }

    for (int ch = 0; ch < 32; ch++) {
        asm volatile("cp.async.wait_group %0;" :: "n"(NSTAGE - 2) : "memory");
        __syncthreads();
        // issue loads for ch+3 (stage ring) — overlaps the mma below
        if (ch + NSTAGE - 1 < 32) {
            int cn = ch + NSTAGE - 1;
            uint32_t bb = base0 + (cn & (NSTAGE - 1)) * BUFSZ;
            size_t g = goff + (size_t)cn * 64;
            cpasync16(bb + sw0, A + g);
            cpasync16(bb + sw1, A + g + 16);
            cpasync16(bb + PLANE + sw0, B + g);
            cpasync16(bb + PLANE + sw1, B + g + 16);
        }
        asm volatile("cp.async.commit_group;" ::: "memory");
        uint32_t baseA = base0 + (ch & (NSTAGE - 1)) * BUFSZ;
        uint32_t baseB = baseA + PLANE;
        // mma phase: 2 k-steps of k16
#pragma unroll
        for (int ks = 0; ks < 2; ks++) {
            uint32_t Af[4][4], Bf[2][4];
            uint32_t akb = ks * 32u + a_kb0;
            uint32_t bkb = ks * 32u + b_kb0;
#pragma unroll
            for (int mt = 0; mt < 4; mt++)
                ldsm4(Af[mt], baseA + swz(a_rb + mt * 16, akb));
#pragma unroll
            for (int np = 0; np < 2; np++)
                ldsm4(Bf[np], baseB + swz(b_rb + np * 16, bkb));
#pragma unroll
            for (int mt = 0; mt < 4; mt++)
#pragma unroll
                for (int np = 0; np < 2; np++)
#pragma unroll
                    for (int hf = 0; hf < 2; hf++) {
                        int nt = np * 2 + hf;
                        mma_f16(acc[mt][nt], Af[mt], Bf[np][hf * 2],
                                Bf[np][hf * 2 + 1]);
                    }
        }
    }

    // epilogue: C frag -> global
#pragma unroll
    for (int mt = 0; mt < 4; mt++) {
        int row0 = t0 + warp_m * 64 + mt * 16 + (lane >> 2);
#pragma unroll
        for (int nt = 0; nt < 4; nt++) {
            int col = d0 + warp_n * 32 + nt * 8 + (lane & 3) * 2;
            float* o0 = out + (size_t)(b * TSZ + row0) * DD + col;
            float* o1 = out + (size_t)(b * TSZ + row0 + 8) * DD + col;
            *(float2*)o0 = make_float2(acc[mt][nt][0], acc[mt][nt][1]);
            *(float2*)o1 = make_float2(acc[mt][nt][2], acc[mt][nt][3]);
        }
    }
}

extern "C" void kernel_launch(void* const* d_in, const int* in_sizes, int n_in,
                              void* d_out, int out_size) {
    const float* x = (const float*)d_in[0];
    const float* ec = (const float*)d_in[1];
    const float* W1 = (const float*)d_in[2];
    const float* b1 = (const float*)d_in[3];
    const float* W2 = (const float*)d_in[4];
    const float* b2 = (const float*)d_in[5];
    const float* W3 = (const float*)d_in[6];
    const float* b3 = (const float*)d_in[7];
    const float* wa = (const float*)d_in[8];
    // d_in[9] = wa_b: cancels in softmax -> unused.
    float* out = (float*)d_out;

    cudaFuncSetAttribute(k4_out_mma, cudaFuncAttributeMaxDynamicSharedMemorySize,
                         K4_DSMEM);

    kx_split<<<dim3(16, 32, 4), 256>>>(x);
    k0_w3e<<<1, 256>>>(ec, W3, b3);
    k1_proj<<<64, 256>>>(x, W1, b1, W2, b2);
    k2_scores<<<dim3(32, 32, 4), 256>>>(wa);
    k3_softmax<<<4096, 256>>>();
    k4_out_mma<<<dim3(4, 8, 4), 256, K4_DSMEM>>>(out);
}

// round 16
// speedup vs baseline: 1.0167x; 1.0167x over previous
#include <cuda_runtime.h>
#include <cuda_bf16.h>
#include <cuda_fp16.h>
#include <cstdint>

#define BB 4
#define TSZ 1024
#define DD 512
#define PP 64
#define MM 256

// Scratch (static device memory; no allocation at runtime)
__device__ float g_a1[BB * TSZ * PP];            // x@W1 + b1 + w3e   (t-side)
__device__ float g_a2[BB * TSZ * PP];            // x@W2 + b2         (u-side)
__device__ float g_w3e[BB * PP];                 // ec@W3 + b3
__device__ float g_att[(size_t)BB * TSZ * TSZ];  // raw scores (16 MB)
// fp16 planes (uint4 arrays for 16B alignment)
__device__ uint4 g_attP4[(size_t)BB * TSZ * TSZ / 8];  // probs fp16 (8 MB)
__device__ uint4 g_xT4[(size_t)BB * DD * TSZ / 8];     // x^T  fp16 (4 MB)

// single-MUFU tanh (MUFU.TANH)
__device__ __forceinline__ float fast_tanh(float x) {
    float y;
    asm("tanh.approx.f32 %0, %1;" : "=f"(y) : "f"(x));
    return y;
}

// ---------------------------------------------------------------- K0: w3e
__global__ void k0_w3e(const float* __restrict__ ec,
                       const float* __restrict__ W3,
                       const float* __restrict__ b3) {
    int tid = threadIdx.x;            // 256 threads: (b,p)
    int b = tid >> 6, p = tid & 63;
    float s = b3[p];
    const float* e = ec + b * MM;
#pragma unroll 8
    for (int m = 0; m < MM; m++) s = fmaf(e[m], W3[m * PP + p], s);
    g_w3e[tid] = s;
}

// ------------------------------- KX: transpose x -> fp16 [b][d][t]
__global__ __launch_bounds__(256) void kx_split(const float* __restrict__ x) {
    __shared__ float tile[32][33];
    int b = blockIdx.z;
    int t0 = blockIdx.y * 32, d0 = blockIdx.x * 32;
    int tx = threadIdx.x & 31, ty = threadIdx.x >> 5;  // 32 x 8
    const float* src = x + (size_t)b * TSZ * DD;
#pragma unroll
    for (int i = 0; i < 4; i++)
        tile[ty + 8 * i][tx] = src[(size_t)(t0 + ty + 8 * i) * DD + d0 + tx];
    __syncthreads();
    __half* oh = (__half*)g_xT4 + (size_t)b * DD * TSZ;
#pragma unroll
    for (int i = 0; i < 4; i++) {
        int d = d0 + ty + 8 * i;
        oh[(size_t)d * TSZ + t0 + tx] = __float2half_rn(tile[tx][ty + 8 * i]);
    }
}

// ------------------------------------------------- K1: fused projections
__global__ __launch_bounds__(256) void k1_proj(const float* __restrict__ x,
                                               const float* __restrict__ W1,
                                               const float* __restrict__ b1,
                                               const float* __restrict__ W2,
                                               const float* __restrict__ b2) {
    __shared__ float XsT[32][68];
    __shared__ float W1s[32][64];
    __shared__ float W2s[32][64];
    int tid = threadIdx.x;
    int r0 = blockIdx.x * 64;
    int tx = tid & 15, ty = tid >> 4;
    float acc1[4][4] = {}, acc2[4][4] = {};

    for (int k0 = 0; k0 < DD; k0 += 32) {
        __syncthreads();
#pragma unroll
        for (int s = 0; s < 2; s++) {
            int f = tid + 256 * s;
            int row = f >> 3, q = f & 7;
            float4 v = *(const float4*)(x + (size_t)(r0 + row) * DD + k0 + q * 4);
            XsT[q * 4 + 0][row] = v.x;
            XsT[q * 4 + 1][row] = v.y;
            XsT[q * 4 + 2][row] = v.z;
            XsT[q * 4 + 3][row] = v.w;
        }
#pragma unroll
        for (int s = 0; s < 2; s++) {
            int row = (tid >> 4) + 16 * s;
            int q = tid & 15;
            *(float4*)&W1s[row][q * 4] =
                *(const float4*)(W1 + (size_t)(k0 + row) * PP + q * 4);
            *(float4*)&W2s[row][q * 4] =
                *(const float4*)(W2 + (size_t)(k0 + row) * PP + q * 4);
        }
        __syncthreads();
#pragma unroll
        for (int kk = 0; kk < 32; kk++) {
            float4 a = *(float4*)&XsT[kk][ty * 4];
            float4 u = *(float4*)&W1s[kk][tx * 4];
            float4 w = *(float4*)&W2s[kk][tx * 4];
            float av[4] = {a.x, a.y, a.z, a.w};
            float uv[4] = {u.x, u.y, u.z, u.w};
            float wv[4] = {w.x, w.y, w.z, w.w};
#pragma unroll
            for (int i = 0; i < 4; i++)
#pragma unroll
                for (int j = 0; j < 4; j++) {
                    acc1[i][j] = fmaf(av[i], uv[j], acc1[i][j]);
                    acc2[i][j] = fmaf(av[i], wv[j], acc2[i][j]);
                }
        }
    }
    int b = r0 >> 10;
    float4 vb1 = *(const float4*)(b1 + tx * 4);
    float4 vb2 = *(const float4*)(b2 + tx * 4);
    float4 v3 = *(const float4*)(g_w3e + b * PP + tx * 4);
#pragma unroll
    for (int i = 0; i < 4; i++) {
        int row = r0 + ty * 4 + i;
        float4 o1, o2;
        o1.x = acc1[i][0] + vb1.x + v3.x;
        o1.y = acc1[i][1] + vb1.y + v3.y;
        o1.z = acc1[i][2] + vb1.z + v3.z;
        o1.w = acc1[i][3] + vb1.w + v3.w;
        o2.x = acc2[i][0] + vb2.x;
        o2.y = acc2[i][1] + vb2.y;
        o2.z = acc2[i][2] + vb2.z;
        o2.w = acc2[i][3] + vb2.w;
        *(float4*)(g_a1 + (size_t)row * PP + tx * 4) = o1;
        *(float4*)(g_a2 + (size_t)row * PP + tx * 4) = o2;
    }
}

// ---------------------------------------------- K2: attention scores (MUFU-bound)
__global__ __launch_bounds__(256) void k2_scores(const float* __restrict__ wa) {
    __shared__ float As[32][65];
    __shared__ float Bs[32][65];
    __shared__ float was[64];
    int tid = threadIdx.x;
    int b = blockIdx.z, t0 = blockIdx.y * 32, u0 = blockIdx.x * 32;
    const float* slabA = g_a1 + (size_t)(b * TSZ + t0) * PP;
    const float* slabB = g_a2 + (size_t)(b * TSZ + u0) * PP;
#pragma unroll
    for (int s = 0; s < 8; s++) {
        int f = tid + 256 * s;
        As[f >> 6][f & 63] = slabA[f];
        Bs[f >> 6][f & 63] = slabB[f];
    }
    if (tid < 64) was[tid] = wa[tid];
    __syncthreads();

    int tu = tid & 15, tt = tid >> 4;
    float a00 = 0.f, a01 = 0.f, a10 = 0.f, a11 = 0.f;
#pragma unroll 8
    for (int p = 0; p < 64; p++) {
        float w = was[p];
        float x0 = As[tt][p], x1 = As[tt + 16][p];
        float y0 = Bs[tu][p], y1 = Bs[tu + 16][p];
        a00 = fmaf(w, fast_tanh(x0 + y0), a00);
        a01 = fmaf(w, fast_tanh(x0 + y1), a01);
        a10 = fmaf(w, fast_tanh(x1 + y0), a10);
        a11 = fmaf(w, fast_tanh(x1 + y1), a11);
    }
    float* o0 = g_att + ((size_t)(b * TSZ + t0 + tt)) * TSZ + u0;
    float* o1 = g_att + ((size_t)(b * TSZ + t0 + tt + 16)) * TSZ + u0;
    o0[tu] = a00;
    o0[tu + 16] = a01;
    o1[tu] = a10;
    o1[tu + 16] = a11;
}

// ---------------------- K3: softmax, writes fp16 prob plane
__global__ __launch_bounds__(256) void k3_softmax() {
    int row = blockIdx.x;  // flat (b*T + t)
    const float* p = g_att + (size_t)row * TSZ;
    int tid = threadIdx.x;
    float v0 = p[tid], v1 = p[tid + 256], v2 = p[tid + 512], v3 = p[tid + 768];
    float m = fmaxf(fmaxf(v0, v1), fmaxf(v2, v3));
#pragma unroll
    for (int o = 16; o; o >>= 1) m = fmaxf(m, __shfl_xor_sync(0xffffffffu, m, o));
    __shared__ float red[8];
    __shared__ float bc[2];
    if ((tid & 31) == 0) red[tid >> 5] = m;
    __syncthreads();
    if (tid == 0) {
        float mm = red[0];
#pragma unroll
        for (int i = 1; i < 8; i++) mm = fmaxf(mm, red[i]);
        bc[0] = mm;
    }
    __syncthreads();
    m = bc[0];
    const float L2E = 1.4426950408889634f;
    float e0, e1, e2, e3;
    asm("ex2.approx.f32 %0, %1;" : "=f"(e0) : "f"((v0 - m) * L2E));
    asm("ex2.approx.f32 %0, %1;" : "=f"(e1) : "f"((v1 - m) * L2E));
    asm("ex2.approx.f32 %0, %1;" : "=f"(e2) : "f"((v2 - m) * L2E));
    asm("ex2.approx.f32 %0, %1;" : "=f"(e3) : "f"((v3 - m) * L2E));
    float s = e0 + e1 + e2 + e3;
#pragma unroll
    for (int o = 16; o; o >>= 1) s += __shfl_xor_sync(0xffffffffu, s, o);
    if ((tid & 31) == 0) red[tid >> 5] = s;
    __syncthreads();
    if (tid == 0) {
        float ss = 0.f;
#pragma unroll
        for (int i = 0; i < 8; i++) ss += red[i];
        bc[1] = 1.0f / ss;
    }
    __syncthreads();
    float inv = bc[1];
    __half* oh = (__half*)g_attP4 + (size_t)row * TSZ;
    oh[tid] = __float2half_rn(e0 * inv);
    oh[tid + 256] = __float2half_rn(e1 * inv);
    oh[tid + 512] = __float2half_rn(e2 * inv);
    oh[tid + 768] = __float2half_rn(e3 * inv);
}

// ================ K4: out = probs @ inputs via fp16 mma.sync =================
// Block tile 128(M) x 64(N), BK=32; grid (8,8,4)=256 CTAs -> ~2 CTAs/SM so
// barrier/ldsm exposure of one CTA hides under the other's mma phase.
// 8 warps in 4(M)x2(N); warp tile 32x32. 4-stage cp.async ring.
// SMEM plane rows x 80B, XOR swizzle bits[4:5] by (row>>3)&3.

__device__ __forceinline__ uint32_t smem_u32(const void* p) {
    uint32_t a;
    asm("{ .reg .u64 t; cvta.to.shared.u64 t, %1; cvt.u32.u64 %0, t; }"
        : "=r"(a) : "l"(p));
    return a;
}
__device__ __forceinline__ uint32_t swz(uint32_t row, uint32_t byteoff) {
    return row * 80u + (byteoff ^ ((row & 24u) << 1));
}
__device__ __forceinline__ void ldsm4(uint32_t r[4], uint32_t addr) {
    asm volatile(
        "ldmatrix.sync.aligned.m8n8.x4.shared.b16 {%0,%1,%2,%3}, [%4];"
        : "=r"(r[0]), "=r"(r[1]), "=r"(r[2]), "=r"(r[3]) : "r"(addr));
}
__device__ __forceinline__ void mma_f16(float c[4], const uint32_t a[4],
                                        uint32_t b0, uint32_t b1) {
    asm volatile(
        "mma.sync.aligned.m16n8k16.row.col.f32.f16.f16.f32 "
        "{%0,%1,%2,%3}, {%4,%5,%6,%7}, {%8,%9}, {%0,%1,%2,%3};"
        : "+f"(c[0]), "+f"(c[1]), "+f"(c[2]), "+f"(c[3])
        : "r"(a[0]), "r"(a[1]), "r"(a[2]), "r"(a[3]), "r"(b0), "r"(b1));
}
__device__ __forceinline__ void cpasync16(uint32_t dst, const void* src) {
    asm volatile("cp.async.cg.shared.global [%0], [%1], 16;"
                 :: "r"(dst), "l"(src) : "memory");
}

#define APLANE 10240u             // 128 rows * 80
#define BPLANE 5120u              // 64 rows * 80
#define BUFSZ (APLANE + BPLANE)   // 15360
#define NSTAGE 4
#define K4_DSMEM (NSTAGE * BUFSZ) // 61440 B

__global__ __launch_bounds__(256) void k4_out_mma(float* __restrict__ out) {
    extern __shared__ uint8_t dsm[];
    uint32_t base0 = smem_u32(dsm);

    int tid = threadIdx.x, wid = tid >> 5, lane = tid & 31;
    int b = blockIdx.z, t0 = blockIdx.y * 128, d0 = blockIdx.x * 64;
    int warp_m = wid >> 1, warp_n = wid & 1;  // 4 x 2

    // fp16 plane pointers (row pitch = TSZ halves = 2048 B)
    const char* A = (const char*)g_attP4 + ((size_t)(b * TSZ + t0) * TSZ) * 2;
    const char* B = (const char*)g_xT4 + ((size_t)b * DD + d0) * TSZ * 2;

    // A: 128 rows x 64B/chunk = 512 x16B -> 2 per thread
    int arow = tid >> 1;
    uint32_t aq = (tid & 1) * 32;
    size_t ga = (size_t)arow * 2048 + aq;
    uint32_t swa0 = swz(arow, aq), swa1 = swz(arow, aq + 16);
    // B: 64 rows x 64B/chunk = 256 x16B -> 1 per thread
    int brow = tid >> 2;
    uint32_t bq = (tid & 3) * 16;
    size_t gb = (size_t)brow * 2048 + bq;
    uint32_t swb = swz(brow, bq);

    float acc[2][4][4] = {};

    int mi = lane >> 3, r8 = lane & 7;
    uint32_t a_rb = warp_m * 32 + (mi & 1) * 8 + r8;
    uint32_t a_kb0 = (mi >> 1) * 16;
    uint32_t b_rb = warp_n * 32 + ((mi >> 1) & 1) * 8 + r8;
    uint32_t b_kb0 = (mi & 1) * 16;

    // prologue: issue chunks 0..2 into stages 0..2
#pragma unroll
    for (int ch = 0; ch < NSTAGE - 1; ch++) {
        uint32_t bb = base0 + ch * BUFSZ;
        size_t off = (size_t)ch * 64;
        cpasync16(bb + swa0, A + ga + off);
        cpasync16(bb + swa1, A + ga + off + 16);
        cpasync16(bb + APLANE + swb, B + gb + off);
        asm volatile("cp.async.commit_group;" ::: "memory");
    }

    for (int ch = 0; ch < 32; ch++) {
        asm volatile("cp.async.wait_group %0;" :: "n"(NSTAGE - 2) : "memory");
        __syncthreads();
        // issue loads for ch+3 (stage ring) — overlaps the mma below
        if (ch + NSTAGE - 1 < 32) {
            int cn = ch + NSTAGE - 1;
            uint32_t bb = base0 + (cn & (NSTAGE - 1)) * BUFSZ;
            size_t off = (size_t)cn * 64;
            cpasync16(bb + swa0, A + ga + off);
            cpasync16(bb + swa1, A + ga + off + 16);
            cpasync16(bb + APLANE + swb, B + gb + off);
        }
        asm volatile("cp.async.commit_group;" ::: "memory");
        uint32_t baseA = base0 + (ch & (NSTAGE - 1)) * BUFSZ;
        uint32_t baseB = baseA + APLANE;
        // mma phase: 2 k-steps of k16
#pragma unroll
        for (int ks = 0; ks < 2; ks++) {
            uint32_t Af[2][4], Bf[2][4];
            uint32_t akb = ks * 32u + a_kb0;
            uint32_t bkb = ks * 32u + b_kb0;
#pragma unroll
            for (int mt = 0; mt < 2; mt++)
                ldsm4(Af[mt], baseA + swz(a_rb + mt * 16, akb));
#pragma unroll
            for (int np = 0; np < 2; np++)
                ldsm4(Bf[np], baseB + swz(b_rb + np * 16, bkb));
#pragma unroll
            for (int mt = 0; mt < 2; mt++)
#pragma unroll
                for (int np = 0; np < 2; np++)
#pragma unroll
                    for (int hf = 0; hf < 2; hf++) {
                        int nt = np * 2 + hf;
                        mma_f16(acc[mt][nt], Af[mt], Bf[np][hf * 2],
                                Bf[np][hf * 2 + 1]);
                    }
        }
    }

    // epilogue: C frag -> global
#pragma unroll
    for (int mt = 0; mt < 2; mt++) {
        int row0 = t0 + warp_m * 32 + mt * 16 + (lane >> 2);
#pragma unroll
        for (int nt = 0; nt < 4; nt++) {
            int col = d0 + warp_n * 32 + nt * 8 + (lane & 3) * 2;
            float* o0 = out + (size_t)(b * TSZ + row0) * DD + col;
            float* o1 = out + (size_t)(b * TSZ + row0 + 8) * DD + col;
            *(float2*)o0 = make_float2(acc[mt][nt][0], acc[mt][nt][1]);
            *(float2*)o1 = make_float2(acc[mt][nt][2], acc[mt][nt][3]);
        }
    }
}

extern "C" void kernel_launch(void* const* d_in, const int* in_sizes, int n_in,
                              void* d_out, int out_size) {
    const float* x = (const float*)d_in[0];
    const float* ec = (const float*)d_in[1];
    const float* W1 = (const float*)d_in[2];
    const float* b1 = (const float*)d_in[3];
    const float* W2 = (const float*)d_in[4];
    const float* b2 = (const float*)d_in[5];
    const float* W3 = (const float*)d_in[6];
    const float* b3 = (const float*)d_in[7];
    const float* wa = (const float*)d_in[8];
    // d_in[9] = wa_b: cancels in softmax -> unused.
    float* out = (float*)d_out;

    cudaFuncSetAttribute(k4_out_mma, cudaFuncAttributeMaxDynamicSharedMemorySize,
                         K4_DSMEM);

    kx_split<<<dim3(16, 32, 4), 256>>>(x);
    k0_w3e<<<1, 256>>>(ec, W3, b3);
    k1_proj<<<64, 256>>>(x, W1, b1, W2, b2);
    k2_scores<<<dim3(32, 32, 4), 256>>>(wa);
    k3_softmax<<<4096, 256>>>();
    k4_out_mma<<<dim3(8, 8, 4), 256, K4_DSMEM>>>(out);
}